// round 16
// baseline (speedup 1.0000x reference)
#include <cuda_runtime.h>
#include <math.h>
#include <stdint.h>

// Problem constants
#define LAYERS 8
#define BATCH  256
#define TIME   8
#define EDIM   1024
#define HDIM   1024
#define KDIM   2048

#define BM     64
#define BK     32
#define KT     32      // 1024 / BK per half-cell
#define STAGES 3

// Scratch buffers
__device__ float g_hseq[(size_t)LAYERS * TIME * BATCH * HDIM]; // per-(l,t) h, rounded+permuted
__device__ float g_crun[LAYERS * BATCH * HDIM];                // per-layer running cell state
__device__ float g_w2[(size_t)4 * LAYERS * KDIM * HDIM];       // packed weights, 268 MB
__device__ float g_xr[BATCH * TIME * EDIM];                    // rounded+permuted x
__device__ float g_h0r[LAYERS * BATCH * HDIM];                 // rounded+permuted h0
__device__ float g_pre[(size_t)2 * TIME * BATCH * 4 * HDIM];   // Gpre double buffer (layer parity)
// Flags: [0,256) hcnt[(l*8+t)*4+bblk] (target 32); [256,8448) xdone[(l*8+t)*128+tile]
#define NFLAGS 8448
__device__ int g_flags[NFLAGS];

__device__ __forceinline__ float f2tf32f(float f) {
    float r;
    asm("{ .reg .b32 t; cvt.rna.tf32.f32 t, %1; mov.b32 %0, t; }" : "=f"(r) : "f"(f));
    return r;
}

__device__ __forceinline__ void mma_tf32(float c[4],
                                         uint32_t a0, uint32_t a1, uint32_t a2, uint32_t a3,
                                         uint32_t b0, uint32_t b1) {
    asm volatile(
        "mma.sync.aligned.m16n8k8.row.col.f32.tf32.tf32.f32 "
        "{%0,%1,%2,%3}, {%4,%5,%6,%7}, {%8,%9}, {%0,%1,%2,%3};"
        : "+f"(c[0]), "+f"(c[1]), "+f"(c[2]), "+f"(c[3])
        : "r"(a0), "r"(a1), "r"(a2), "r"(a3), "r"(b0), "r"(b1));
}

__device__ __forceinline__ void cp16(uint32_t dst, const float* src) {
    asm volatile("cp.async.cg.shared.global [%0], [%1], 16;" :: "r"(dst), "l"(src));
}
__device__ __forceinline__ void cp_commit() {
    asm volatile("cp.async.commit_group;");
}
template <int N> __device__ __forceinline__ void cp_wait() {
    asm volatile("cp.async.wait_group %0;" :: "n"(N));
}

__device__ __forceinline__ void wait_ge(volatile int* p, int v) {
    while (*p < v)
        asm volatile("nanosleep.u32 128;");
}

// ---------------------------------------------------------------------------
// Prep kernels.
// Interleaved-pair layout: k-groups of 8 stored as pairs (k, k+4):
// pos(k) = 2*(k&3) + ((k>>2)&1). Fragment pair -> one aligned float2 LDS.
// ---------------------------------------------------------------------------
__global__ __launch_bounds__(256)
void prep_act(const float4* __restrict__ x, float4* __restrict__ xr, size_t n8x,
              const float4* __restrict__ h0, float4* __restrict__ h0r, size_t n8h) {
    size_t i = (size_t)blockIdx.x * blockDim.x + threadIdx.x;
    const size_t stride = (size_t)gridDim.x * blockDim.x;
    const size_t total = n8x + n8h;
    for (; i < total; i += stride) {
        const float4* s = (i < n8x) ? (x + 2 * i) : (h0 + 2 * (i - n8x));
        float4* d       = (i < n8x) ? (xr + 2 * i) : (h0r + 2 * (i - n8x));
        float4 a = s[0];
        float4 b = s[1];
        d[0] = make_float4(f2tf32f(a.x), f2tf32f(b.x), f2tf32f(a.y), f2tf32f(b.y));
        d[1] = make_float4(f2tf32f(a.z), f2tf32f(b.z), f2tf32f(a.w), f2tf32f(b.w));
    }
}

// All 4 gates in one launch. W[g][l][k][j] -> W2 float2 pairs (W[k_lo][j],
// W[k_lo+4][j]), kp = (k_lo>>3)*4 + (k_lo&3), tf32-rounded.
__global__ __launch_bounds__(256)
void prep_w(const float* __restrict__ Wu, const float* __restrict__ Wf,
            const float* __restrict__ Wo, const float* __restrict__ Wc,
            float* __restrict__ W2, size_t njobs) {
    const size_t GSZ = (size_t)LAYERS * KDIM * HDIM;
    size_t i = (size_t)blockIdx.x * blockDim.x + threadIdx.x;
    const size_t stride = (size_t)gridDim.x * blockDim.x;
    for (; i < njobs; i += stride) {
        const int j4 = (int)(i & 255) * 4;
        const int kp = (int)(i >> 8) & 1023;
        const int l  = (int)(i >> 18) & 7;
        const int g  = (int)(i >> 21);
        const int k_lo = (kp >> 2) * 8 + (kp & 3);
        const float* W = (g == 0) ? Wu : (g == 1) ? Wf : (g == 2) ? Wo : Wc;
        const float* src = W + ((size_t)l * KDIM + k_lo) * HDIM + j4;
        float4 lo = *(const float4*)src;
        float4 hi = *(const float4*)(src + 4 * HDIM);
        float* d = W2 + (size_t)g * GSZ + ((size_t)l * 1024 + kp) * 2048 + (size_t)j4 * 2;
        *(float4*)d       = make_float4(f2tf32f(lo.x), f2tf32f(hi.x),
                                        f2tf32f(lo.y), f2tf32f(hi.y));
        *(float4*)(d + 4) = make_float4(f2tf32f(lo.z), f2tf32f(hi.z),
                                        f2tf32f(lo.w), f2tf32f(hi.w));
    }
}

// -----------------------------------------------------------------------------
// GEMM mainloop, K = 1024, float2-fragment loads.
// A tile: 64 rows x 32 floats (pair-interleaved), row stride 40 floats.
// B tile: 4 gates x 16 pair-rows x 32 float2, pair-row stride 72 floats.
// W2 pointers must already point at the correct K-half (kp offset).
// -----------------------------------------------------------------------------
#define A_STR   40
#define B_STR   72
#define A_F     (64 * A_STR)               // 2560 floats
#define B_GATE  (16 * B_STR)               // 1152 floats
#define STAGE_F (A_F + 4 * B_GATE)         // 7168 floats

__device__ __forceinline__ void gemm_k1024(
    float* smem,
    const float* __restrict__ Aptr, int strideA, int r0,
    const float* __restrict__ W2u, const float* __restrict__ W2f,
    const float* __restrict__ W2o, const float* __restrict__ W2c,
    int j0, float acc[2][4][4])
{
    const int tid  = threadIdx.x;
    const int lane = tid & 31;
    const int warp = tid >> 5;
    const int wy   = warp >> 2;
    const int wx   = warp & 3;
    const int g4   = lane >> 2;
    const int t4   = lane & 3;

    // A cp.async mapping: 64 rows x 8 segs(16B); 2 segs/thread
    const int aRow = tid >> 2;
    const int aSeg = tid & 3;
    const float* aSrc = Aptr + (size_t)(r0 + aRow) * strideA;
    float* const aDst0 = smem + aRow * A_STR + aSeg * 4;

    // B cp.async mapping: 64 (gate,prow) x 16 segs(16B); 4 segs/thread
    const int prow_g = tid >> 2;
    const int gateB  = prow_g >> 4;
    const int pB     = prow_g & 15;
    const int segB   = (tid & 3) * 4;
    const float* W2sel = (gateB == 0) ? W2u : (gateB == 1) ? W2f
                       : (gateB == 2) ? W2o : W2c;
    const float* wSrcBase = W2sel + ((size_t)pB * 1024 + j0) * 2 + (size_t)segB * 4;
    float* const bDst = smem + A_F + gateB * B_GATE + pB * B_STR + segB * 4;

    auto issue = [&](int c) {
        const float* s = aSrc + c * BK;
        float* aD = aDst0 + (c % STAGES) * STAGE_F;
        cp16((uint32_t)__cvta_generic_to_shared(aD),      s + aSeg * 4);
        cp16((uint32_t)__cvta_generic_to_shared(aD + 16), s + (aSeg + 4) * 4);
        const float* ws = wSrcBase + (size_t)c * (16 * 2048);
        float* wd = bDst + (c % STAGES) * STAGE_F;
        #pragma unroll
        for (int q = 0; q < 4; q++)
            cp16((uint32_t)__cvta_generic_to_shared(wd + q * 4), ws + q * 4);
        cp_commit();
    };

    auto compute = [&](int slot) {
        const float* sA  = smem + slot * STAGE_F;
        const float* sBg = sA + A_F + wx * B_GATE;
        #pragma unroll
        for (int q = 0; q < 4; q++) {
            float2 A0[2], A1[2];
            #pragma unroll
            for (int mi = 0; mi < 2; mi++) {
                const float* pa = sA + (32 * wy + 16 * mi + g4) * A_STR
                                + (4 * q + t4) * 2;
                A0[mi] = *(const float2*)pa;
                A1[mi] = *(const float2*)(pa + 8 * A_STR);
            }
            #pragma unroll
            for (int ni = 0; ni < 4; ni++) {
                const float2 Bf = *(const float2*)(sBg + ((4 * q + t4) * B_STR
                                                          + (8 * ni + g4) * 2));
                const uint32_t b0 = __float_as_uint(Bf.x);
                const uint32_t b1 = __float_as_uint(Bf.y);
                mma_tf32(acc[0][ni],
                         __float_as_uint(A0[0].x), __float_as_uint(A1[0].x),
                         __float_as_uint(A0[0].y), __float_as_uint(A1[0].y), b0, b1);
                mma_tf32(acc[1][ni],
                         __float_as_uint(A0[1].x), __float_as_uint(A1[1].x),
                         __float_as_uint(A0[1].y), __float_as_uint(A1[1].y), b0, b1);
            }
        }
    };

    issue(0);
    issue(1);
    #pragma unroll 1
    for (int c = 0; c < KT; c++) {
        cp_wait<STAGES - 2>();
        __syncthreads();
        if (c + 2 < KT) issue(c + 2); else cp_commit();
        compute(c % STAGES);
    }
}

// ---------------------------------------------------------------------------
// Fused split-cell DAG kernel.
// Dispatch order: x(0, t=0..7) [1024 CTAs], then for l=0..7, t=0..7:
//   h(l,t) [128], followed by x(l+1,t) [128] (if l<7).
// x-cell (l,t): x-part K=1024 GEMM -> Gpre[l&1][t]. Waits hcnt(l-1,t,bblk)==32.
// h-cell (l,t): h-part K=1024 GEMM + Gpre + cell update. Waits own x tile and
//   hcnt(l,t-1,bblk)==32.
// ---------------------------------------------------------------------------
#define GS_STRIDE 130

__global__ __launch_bounds__(256, 2)
void lstm_dag(const float* __restrict__ xr, const float* __restrict__ h0r,
              const float* __restrict__ c0,
              const float* __restrict__ w2,
              const float* __restrict__ bu, const float* __restrict__ bf,
              const float* __restrict__ bo, const float* __restrict__ bc,
              float* __restrict__ crun, float* __restrict__ hseq,
              float* __restrict__ gpre,
              float* __restrict__ outH, float* __restrict__ outC,
              float* __restrict__ outHt, float* __restrict__ outCt)
{
    extern __shared__ float smem[];
    const int tid = threadIdx.x;

    // Decode block -> (isH, l, t, tile)
    int isH, l, t, tile;
    {
        const int bid = blockIdx.x;
        if (bid < 1024) {
            isH = 0; l = 0; t = bid >> 7; tile = bid & 127;
        } else {
            const int g = (bid - 1024) >> 7;
            tile = bid & 127;
            if (g < 112) {
                const int p = g >> 1;
                if (g & 1) { isH = 0; l = p / 8 + 1; t = p % 8; }
                else       { isH = 1; l = p / 8;     t = p % 8; }
            } else {
                isH = 1; l = 7; t = g - 112;
            }
        }
    }
    const int jblk = tile & 31, bblk = tile >> 5;
    const int j0 = jblk * 32, b0 = bblk * BM;

    const size_t GSZ  = (size_t)LAYERS * KDIM * HDIM;
    const size_t lOff = (size_t)l * KDIM * HDIM;
    const int cellid = l * TIME + t;
    float* gp = gpre + ((size_t)((l & 1) * TIME + t)) * (BATCH * 4 * HDIM);

    float acc[2][4][4];
    #pragma unroll
    for (int mi = 0; mi < 2; mi++)
        #pragma unroll
        for (int ni = 0; ni < 4; ni++)
            #pragma unroll
            for (int r = 0; r < 4; r++) acc[mi][ni][r] = 0.0f;

    if (!isH) {
        // ---------------- x-cell ----------------
        if (tid == 0 && l > 0) {
            wait_ge(&g_flags[((l - 1) * TIME + t) * 4 + bblk], 32);
            __threadfence();
        }
        __syncthreads();

        const float* inA; int strideIn;
        if (l == 0) { inA = xr + (size_t)t * EDIM; strideIn = TIME * EDIM; }
        else {
            inA = hseq + ((size_t)(l - 1) * TIME + t) * BATCH * HDIM;
            strideIn = HDIM;
        }
        // x-half weights: kp offset 0
        gemm_k1024(smem, inA, strideIn, b0,
                   w2 + lOff, w2 + GSZ + lOff, w2 + 2 * GSZ + lOff, w2 + 3 * GSZ + lOff,
                   j0, acc);
        cp_wait<0>();

        // Write raw preacts to Gpre[(b*4+gate)*H + j]
        const int lane = tid & 31;
        const int warp = tid >> 5;
        const int wy = warp >> 2, wx = warp & 3;
        const int g4 = lane >> 2, t4 = lane & 3;
        #pragma unroll
        for (int mi = 0; mi < 2; mi++) {
            #pragma unroll
            for (int ni = 0; ni < 4; ni++) {
                const int row = b0 + 32 * wy + 16 * mi + g4;
                const int col = j0 + 8 * ni + 2 * t4;
                *(float2*)(gp + ((size_t)row * 4 + wx) * HDIM + col) =
                    make_float2(acc[mi][ni][0], acc[mi][ni][1]);
                *(float2*)(gp + ((size_t)(row + 8) * 4 + wx) * HDIM + col) =
                    make_float2(acc[mi][ni][2], acc[mi][ni][3]);
            }
        }
        __threadfence();
        __syncthreads();
        if (tid == 0) atomicAdd(&g_flags[256 + cellid * 128 + tile], 1);
        return;
    }

    // ---------------- h-cell ----------------
    if (tid == 0) {
        wait_ge(&g_flags[256 + cellid * 128 + tile], 1);       // own x tile
        if (t > 0)
            wait_ge(&g_flags[(l * TIME + (t - 1)) * 4 + bblk], 32);
        __threadfence();
    }
    __syncthreads();

    const float* hB = (t == 0) ? (h0r + (size_t)l * BATCH * HDIM)
                               : (hseq + ((size_t)l * TIME + (t - 1)) * BATCH * HDIM);
    // h-half weights: kp offset 512 -> 512*2048 floats
    const size_t hOff = (size_t)512 * 2048;
    gemm_k1024(smem, hB, HDIM, b0,
               w2 + lOff + hOff, w2 + GSZ + lOff + hOff,
               w2 + 2 * GSZ + lOff + hOff, w2 + 3 * GSZ + lOff + hOff,
               j0, acc);
    cp_wait<0>();
    __syncthreads();

    // Gate exchange through smem: 64 rows x (4 gates x 32 cols)
    float* gs = smem;
    {
        const int lane = tid & 31;
        const int warp = tid >> 5;
        const int wy = warp >> 2, wx = warp & 3;
        const int g4 = lane >> 2, t4 = lane & 3;
        #pragma unroll
        for (int mi = 0; mi < 2; mi++) {
            #pragma unroll
            for (int ni = 0; ni < 4; ni++) {
                const int row = 32 * wy + 16 * mi + g4;
                const int col = wx * 32 + 8 * ni + 2 * t4;
                *(float2*)(gs + row * GS_STRIDE + col) =
                    make_float2(acc[mi][ni][0], acc[mi][ni][1]);
                *(float2*)(gs + (row + 8) * GS_STRIDE + col) =
                    make_float2(acc[mi][ni][2], acc[mi][ni][3]);
            }
        }
    }
    __syncthreads();

    const int jj = tid & 31;
    const int r0 = tid >> 5;
    const int j  = j0 + jj;
    const int j_p = (j & ~7) | ((j & 3) << 1) | ((j >> 2) & 1);
    const float b_u = bu[l * HDIM + j], b_f = bf[l * HDIM + j];
    const float b_o = bo[l * HDIM + j], b_c = bc[l * HDIM + j];

    float* cl = crun + (size_t)l * BATCH * HDIM;
    const float* colds = (t == 0) ? (c0 + (size_t)l * BATCH * HDIM) : cl;
    float* hdst = hseq + ((size_t)l * TIME + t) * BATCH * HDIM;
    const bool last = (l == LAYERS - 1);

    #pragma unroll
    for (int i = 0; i < 8; i++) {
        const int row = r0 + 8 * i;
        const int b   = b0 + row;
        const size_t gbase = (size_t)b * 4 * HDIM + j;
        const float su = gs[row * GS_STRIDE +      jj] + gp[gbase]            + b_u;
        const float sf = gs[row * GS_STRIDE + 32 + jj] + gp[gbase +     HDIM] + b_f;
        const float so = gs[row * GS_STRIDE + 64 + jj] + gp[gbase + 2 * HDIM] + b_o;
        const float sc = gs[row * GS_STRIDE + 96 + jj] + gp[gbase + 3 * HDIM] + b_c;
        const float u  = 1.0f / (1.0f + expf(-su));
        const float f  = 1.0f / (1.0f + expf(-sf));
        const float o  = 1.0f / (1.0f + expf(-so));
        const float ct = tanhf(sc);
        const size_t idx = (size_t)b * HDIM + j;
        const float c_new = f * colds[idx] + u * ct;
        const float h_new = o * tanhf(c_new);
        cl[idx] = c_new;
        hdst[(size_t)b * HDIM + j_p] = f2tf32f(h_new);
        if (last) {
            const size_t oidx = ((size_t)b * TIME + t) * HDIM + j;
            outH[oidx] = h_new;
            outC[oidx] = c_new;
            if (t == TIME - 1) { outHt[idx] = h_new; outCt[idx] = c_new; }
        }
    }

    __threadfence();
    __syncthreads();
    if (tid == 0) atomicAdd(&g_flags[cellid * 4 + bblk], 1);
}

extern "C" void kernel_launch(void* const* d_in, const int* in_sizes, int n_in,
                              void* d_out, int out_size) {
    const float* x  = (const float*)d_in[0];   // (B, T, E)
    const float* h0 = (const float*)d_in[1];   // (L, B, H)
    const float* c0 = (const float*)d_in[2];   // (L, B, H)
    const float* Wu = (const float*)d_in[3];   // (L, 2048, H)
    const float* bu = (const float*)d_in[4];   // (L, H)
    const float* Wf = (const float*)d_in[5];
    const float* bf = (const float*)d_in[6];
    const float* Wo = (const float*)d_in[7];
    const float* bo = (const float*)d_in[8];
    const float* Wc = (const float*)d_in[9];
    const float* bc = (const float*)d_in[10];

    float* out = (float*)d_out;
    float* outHidden = out;                                   // (B, T, H)
    float* outMem    = out + (size_t)BATCH * TIME * HDIM;     // (B, T, H)
    float* outHt     = out + (size_t)2 * BATCH * TIME * HDIM; // (B, 1, H)
    float* outCt     = outHt + (size_t)BATCH * HDIM;          // (B, 1, H)

    float *hseq, *crun, *w2, *xr, *h0r, *gpre;
    int* flags;
    cudaGetSymbolAddress((void**)&hseq,  g_hseq);
    cudaGetSymbolAddress((void**)&crun,  g_crun);
    cudaGetSymbolAddress((void**)&w2,    g_w2);
    cudaGetSymbolAddress((void**)&xr,    g_xr);
    cudaGetSymbolAddress((void**)&h0r,   g_h0r);
    cudaGetSymbolAddress((void**)&gpre,  g_pre);
    cudaGetSymbolAddress((void**)&flags, g_flags);

    // Reset dependency flags (capture-legal memset node).
    cudaMemsetAsync(flags, 0, NFLAGS * sizeof(int), 0);

    // Prep: pack weights + round/permute activations.
    prep_w<<<16384, 256>>>(Wu, Wf, Wo, Wc, w2, (size_t)4 * LAYERS * 1024 * 256);
    prep_act<<<2048, 256>>>((const float4*)x,  (float4*)xr,
                            (size_t)BATCH * TIME * EDIM / 8,
                            (const float4*)h0, (float4*)h0r,
                            (size_t)LAYERS * BATCH * HDIM / 8);

    const int GSMEM = STAGES * STAGE_F * 4;   // 86016 B
    cudaFuncSetAttribute(lstm_dag, cudaFuncAttributeMaxDynamicSharedMemorySize, GSMEM);

    // Single DAG launch: 1024 x(0,*) CTAs + 120 groups of 128.
    const int NBLOCKS = 1024 + 120 * 128;   // 16384
    lstm_dag<<<NBLOCKS, 256, GSMEM>>>(
        xr, h0r, c0, w2, bu, bf, bo, bc,
        crun, hseq, gpre, outHidden, outMem, outHt, outCt);
}

// round 17
// speedup vs baseline: 1.4220x; 1.4220x over previous
#include <cuda_runtime.h>
#include <math.h>
#include <stdint.h>

// Problem constants
#define LAYERS 8
#define BATCH  256
#define TIME   8
#define EDIM   1024
#define HDIM   1024
#define KDIM   2048

#define BM     64
#define BK     32
#define KT2    64      // 2048 / BK
#define STAGES 3
#define NCELLS (LAYERS * TIME)

// Scratch buffers
__device__ float g_hseq[(size_t)LAYERS * TIME * BATCH * HDIM]; // per-(l,t) h, rounded+permuted
__device__ float g_crun[LAYERS * BATCH * HDIM];                // per-layer running cell state
__device__ float g_w2[(size_t)4 * LAYERS * KDIM * HDIM];       // packed weights, 268 MB
__device__ float g_xr[BATCH * TIME * EDIM];                    // rounded+permuted x
__device__ float g_h0r[LAYERS * BATCH * HDIM];                 // rounded+permuted h0
__device__ int   g_cnt[NCELLS * 4];                            // per-(cell,bblk) counters

__device__ __forceinline__ float f2tf32f(float f) {
    float r;
    asm("{ .reg .b32 t; cvt.rna.tf32.f32 t, %1; mov.b32 %0, t; }" : "=f"(r) : "f"(f));
    return r;
}

__device__ __forceinline__ void mma_tf32(float c[4],
                                         uint32_t a0, uint32_t a1, uint32_t a2, uint32_t a3,
                                         uint32_t b0, uint32_t b1) {
    asm volatile(
        "mma.sync.aligned.m16n8k8.row.col.f32.tf32.tf32.f32 "
        "{%0,%1,%2,%3}, {%4,%5,%6,%7}, {%8,%9}, {%0,%1,%2,%3};"
        : "+f"(c[0]), "+f"(c[1]), "+f"(c[2]), "+f"(c[3])
        : "r"(a0), "r"(a1), "r"(a2), "r"(a3), "r"(b0), "r"(b1));
}

__device__ __forceinline__ void cp16(uint32_t dst, const float* src) {
    asm volatile("cp.async.cg.shared.global [%0], [%1], 16;" :: "r"(dst), "l"(src));
}
__device__ __forceinline__ void cp_commit() {
    asm volatile("cp.async.commit_group;");
}
template <int N> __device__ __forceinline__ void cp_wait() {
    asm volatile("cp.async.wait_group %0;" :: "n"(N));
}

// ---------------------------------------------------------------------------
// Wavefront cell numbering helpers
// ---------------------------------------------------------------------------
__device__ __forceinline__ int cell_index(int l, int t) {
    const int wv = l + t;
    int base = 0;
    for (int w = 0; w < wv; w++) {
        const int l_lo = (w - (TIME - 1) > 0) ? (w - (TIME - 1)) : 0;
        const int l_hi = (w < LAYERS - 1) ? w : (LAYERS - 1);
        base += l_hi - l_lo + 1;
    }
    const int l_lo = (wv - (TIME - 1) > 0) ? (wv - (TIME - 1)) : 0;
    return base + (l - l_lo);
}

__device__ __forceinline__ void cell_decode(int cell, int& l, int& t) {
    int wv = 0, base = 0;
    for (;;) {
        const int l_lo = (wv - (TIME - 1) > 0) ? (wv - (TIME - 1)) : 0;
        const int l_hi = (wv < LAYERS - 1) ? wv : (LAYERS - 1);
        const int n = l_hi - l_lo + 1;
        if (cell < base + n) { l = l_lo + (cell - base); break; }
        base += n; wv++;
    }
    t = wv - l;
}

__device__ __forceinline__ void wait_ge(volatile int* p, int v) {
    while (*p < v)
        asm volatile("nanosleep.u32 128;");
}

// ---------------------------------------------------------------------------
// Prep kernels (2 launches).
// Interleaved-pair layout: k-groups of 8 stored as pairs (k, k+4):
// pos(k) = 2*(k&3) + ((k>>2)&1). Fragment pair -> one aligned float2 LDS.
// ---------------------------------------------------------------------------
__global__ __launch_bounds__(256)
void prep_act(const float4* __restrict__ x, float4* __restrict__ xr, size_t n8x,
              const float4* __restrict__ h0, float4* __restrict__ h0r, size_t n8h) {
    size_t i = (size_t)blockIdx.x * blockDim.x + threadIdx.x;
    const size_t stride = (size_t)gridDim.x * blockDim.x;
    const size_t total = n8x + n8h;
    for (; i < total; i += stride) {
        const float4* s = (i < n8x) ? (x + 2 * i) : (h0 + 2 * (i - n8x));
        float4* d       = (i < n8x) ? (xr + 2 * i) : (h0r + 2 * (i - n8x));
        float4 a = s[0];
        float4 b = s[1];
        d[0] = make_float4(f2tf32f(a.x), f2tf32f(b.x), f2tf32f(a.y), f2tf32f(b.y));
        d[1] = make_float4(f2tf32f(a.z), f2tf32f(b.z), f2tf32f(a.w), f2tf32f(b.w));
    }
}

// All 4 gates in one launch. W[g][l][k][j] -> W2 float2 pairs (W[k_lo][j],
// W[k_lo+4][j]), kp = (k_lo>>3)*4 + (k_lo&3), tf32-rounded.
__global__ __launch_bounds__(256)
void prep_w(const float* __restrict__ Wu, const float* __restrict__ Wf,
            const float* __restrict__ Wo, const float* __restrict__ Wc,
            float* __restrict__ W2, size_t njobs) {
    const size_t GSZ = (size_t)LAYERS * KDIM * HDIM;
    size_t i = (size_t)blockIdx.x * blockDim.x + threadIdx.x;
    const size_t stride = (size_t)gridDim.x * blockDim.x;
    for (; i < njobs; i += stride) {
        const int j4 = (int)(i & 255) * 4;
        const int kp = (int)(i >> 8) & 1023;
        const int l  = (int)(i >> 18) & 7;
        const int g  = (int)(i >> 21);
        const int k_lo = (kp >> 2) * 8 + (kp & 3);
        const float* W = (g == 0) ? Wu : (g == 1) ? Wf : (g == 2) ? Wo : Wc;
        const float* src = W + ((size_t)l * KDIM + k_lo) * HDIM + j4;
        float4 lo = *(const float4*)src;
        float4 hi = *(const float4*)(src + 4 * HDIM);
        float* d = W2 + (size_t)g * GSZ + ((size_t)l * 1024 + kp) * 2048 + (size_t)j4 * 2;
        *(float4*)d       = make_float4(f2tf32f(lo.x), f2tf32f(hi.x),
                                        f2tf32f(lo.y), f2tf32f(hi.y));
        *(float4*)(d + 4) = make_float4(f2tf32f(lo.z), f2tf32f(hi.z),
                                        f2tf32f(lo.w), f2tf32f(hi.w));
    }
}

// -----------------------------------------------------------------------------
// GEMM mainloop, K = 2048 = [input 1024 | h 1024], float2-fragment loads.
// A tile: 64 rows x 32 floats (pair-interleaved), row stride 40 floats.
// B tile: 4 gates x 16 pair-rows x 32 float2, pair-row stride 72 floats.
// B (weights) for stages 0,1 is prefetched BEFORE dep_wait(); A after.
// Group order: B0,B1,A0,A1, S2, S3, ... -> uniform cp_wait<1> keeps stage c
// ready at iteration c (checked for c = 0, 1, >=2).
// -----------------------------------------------------------------------------
#define A_STR   40
#define B_STR   72
#define A_F     (64 * A_STR)               // 2560 floats
#define B_GATE  (16 * B_STR)               // 1152 floats
#define STAGE_F (A_F + 4 * B_GATE)         // 7168 floats

template <typename WaitFn>
__device__ __forceinline__ void gemm_k2048(
    float* smem,
    const float* __restrict__ inA, int strideIn,      // k in [0,1024), packed rows
    const float* __restrict__ hB,                     // k in [1024,2048), stride HDIM
    int r0,
    const float* __restrict__ W2u, const float* __restrict__ W2f,
    const float* __restrict__ W2o, const float* __restrict__ W2c, // per-layer packed
    int j0, float acc[2][4][4], WaitFn dep_wait)
{
    const int tid  = threadIdx.x;
    const int lane = tid & 31;
    const int warp = tid >> 5;
    const int wy   = warp >> 2;
    const int wx   = warp & 3;
    const int g4   = lane >> 2;
    const int t4   = lane & 3;

    // A cp.async mapping: 64 rows x 8 segs(16B); 2 segs/thread
    const int aRow = tid >> 2;
    const int aSeg = tid & 3;
    const float* aSrcIn = inA + (size_t)(r0 + aRow) * strideIn;
    const float* aSrcH  = hB  + (size_t)(r0 + aRow) * HDIM;
    float* const aDst0 = smem + aRow * A_STR + aSeg * 4;

    // B cp.async mapping: 64 (gate,prow) x 16 segs(16B); 4 segs/thread
    const int prow_g = tid >> 2;             // 0..63 = gate*16 + p
    const int gateB  = prow_g >> 4;
    const int pB     = prow_g & 15;
    const int segB   = (tid & 3) * 4;
    const float* W2sel = (gateB == 0) ? W2u : (gateB == 1) ? W2f
                       : (gateB == 2) ? W2o : W2c;
    const float* wSrcBase = W2sel + ((size_t)pB * 1024 + j0) * 2 + (size_t)segB * 4;
    float* const bDst = smem + A_F + gateB * B_GATE + pB * B_STR + segB * 4;

    auto issueA = [&](int c) {
        const int k0 = c * BK;
        const float* s = (k0 < EDIM) ? (aSrcIn + k0) : (aSrcH + (k0 - EDIM));
        float* aD = aDst0 + (c % STAGES) * STAGE_F;
        cp16((uint32_t)__cvta_generic_to_shared(aD),      s + aSeg * 4);
        cp16((uint32_t)__cvta_generic_to_shared(aD + 16), s + (aSeg + 4) * 4);
    };

    auto issueB = [&](int c) {
        const float* ws = wSrcBase + (size_t)c * (16 * 2048);
        float* wd = bDst + (c % STAGES) * STAGE_F;
        #pragma unroll
        for (int q = 0; q < 4; q++)
            cp16((uint32_t)__cvta_generic_to_shared(wd + q * 4), ws + q * 4);
    };

    auto compute = [&](int slot) {
        const float* sA  = smem + slot * STAGE_F;
        const float* sBg = sA + A_F + wx * B_GATE;
        #pragma unroll
        for (int q = 0; q < 4; q++) {
            float2 A0[2], A1[2];
            #pragma unroll
            for (int mi = 0; mi < 2; mi++) {
                const float* pa = sA + (32 * wy + 16 * mi + g4) * A_STR
                                + (4 * q + t4) * 2;
                A0[mi] = *(const float2*)pa;
                A1[mi] = *(const float2*)(pa + 8 * A_STR);
            }
            #pragma unroll
            for (int ni = 0; ni < 4; ni++) {
                const float2 Bf = *(const float2*)(sBg + ((4 * q + t4) * B_STR
                                                          + (8 * ni + g4) * 2));
                const uint32_t b0 = __float_as_uint(Bf.x);
                const uint32_t b1 = __float_as_uint(Bf.y);
                mma_tf32(acc[0][ni],
                         __float_as_uint(A0[0].x), __float_as_uint(A1[0].x),
                         __float_as_uint(A0[0].y), __float_as_uint(A1[0].y), b0, b1);
                mma_tf32(acc[1][ni],
                         __float_as_uint(A0[1].x), __float_as_uint(A1[1].x),
                         __float_as_uint(A0[1].y), __float_as_uint(A1[1].y), b0, b1);
            }
        }
    };

    // Prologue: weights (no dependency) in flight during the producer spin.
    issueB(0); cp_commit();        // g0
    issueB(1); cp_commit();        // g1
    dep_wait();                    // spin on producer counters (+ sync)
    issueA(0); cp_commit();        // g2
    issueA(1); cp_commit();        // g3

    #pragma unroll 1
    for (int c = 0; c < KT2; c++) {
        cp_wait<1>();
        __syncthreads();
        if (c + 2 < KT2) { issueA(c + 2); issueB(c + 2); }
        cp_commit();
        compute(c % STAGES);
    }
}

// ---------------------------------------------------------------------------
// Fused DAG kernel: 64 cells x 128 CTAs, topological (wavefront) blockIdx
// order; per-(cell,bblk) flags (target 32) enforce dependencies at
// batch-quarter granularity.
// ---------------------------------------------------------------------------
#define GS_STRIDE 130

__global__ __launch_bounds__(256, 2)
void lstm_fused(const float* __restrict__ xr, const float* __restrict__ h0r,
                const float* __restrict__ c0,
                const float* __restrict__ w2,
                const float* __restrict__ bu, const float* __restrict__ bf,
                const float* __restrict__ bo, const float* __restrict__ bc,
                float* __restrict__ crun, float* __restrict__ hseq,
                float* __restrict__ outH, float* __restrict__ outC,
                float* __restrict__ outHt, float* __restrict__ outCt)
{
    extern __shared__ float smem[];
    const int cell = blockIdx.x >> 7;
    const int tile = blockIdx.x & 127;
    const int jblk = tile & 31, bblk = tile >> 5;
    const int j0 = jblk * 32;
    const int b0 = bblk * BM;
    const int tid = threadIdx.x;

    int l, t;
    cell_decode(cell, l, t);

    // Cell operand pointers
    const float* inA; int strideIn;
    if (l == 0) { inA = xr + (size_t)t * EDIM; strideIn = TIME * EDIM; }
    else {
        inA = hseq + ((size_t)(l - 1) * TIME + t) * BATCH * HDIM;
        strideIn = HDIM;
    }
    const float* hB = (t == 0) ? (h0r + (size_t)l * BATCH * HDIM)
                               : (hseq + ((size_t)l * TIME + (t - 1)) * BATCH * HDIM);
    const size_t GSZ  = (size_t)LAYERS * KDIM * HDIM;
    const size_t lOff = (size_t)l * KDIM * HDIM;

    float acc[2][4][4];
    #pragma unroll
    for (int mi = 0; mi < 2; mi++)
        #pragma unroll
        for (int ni = 0; ni < 4; ni++)
            #pragma unroll
            for (int r = 0; r < 4; r++) acc[mi][ni][r] = 0.0f;

    auto dep_wait = [&]() {
        if (tid == 0) {
            if (l > 0) wait_ge(&g_cnt[cell_index(l - 1, t) * 4 + bblk], 32);
            if (t > 0) wait_ge(&g_cnt[cell_index(l, t - 1) * 4 + bblk], 32);
            __threadfence();
        }
        __syncthreads();
    };

    gemm_k2048(smem, inA, strideIn, hB, b0,
               w2 + lOff, w2 + GSZ + lOff, w2 + 2 * GSZ + lOff, w2 + 3 * GSZ + lOff,
               j0, acc, dep_wait);

    cp_wait<0>();
    __syncthreads();

    // Gate exchange through smem: 64 rows x (4 gates x 32 cols)
    float* gs = smem;
    {
        const int lane = tid & 31;
        const int warp = tid >> 5;
        const int wy = warp >> 2, wx = warp & 3;
        const int g4 = lane >> 2, t4 = lane & 3;
        #pragma unroll
        for (int mi = 0; mi < 2; mi++) {
            #pragma unroll
            for (int ni = 0; ni < 4; ni++) {
                const int row = 32 * wy + 16 * mi + g4;
                const int col = wx * 32 + 8 * ni + 2 * t4;
                *(float2*)(gs + row * GS_STRIDE + col) =
                    make_float2(acc[mi][ni][0], acc[mi][ni][1]);
                *(float2*)(gs + (row + 8) * GS_STRIDE + col) =
                    make_float2(acc[mi][ni][2], acc[mi][ni][3]);
            }
        }
    }
    __syncthreads();

    const int jj = tid & 31;
    const int r0 = tid >> 5;
    const int j  = j0 + jj;
    // Permuted column for packed-h write: pos(k) = 2*(k&3) + ((k>>2)&1)
    const int j_p = (j & ~7) | ((j & 3) << 1) | ((j >> 2) & 1);
    const float b_u = bu[l * HDIM + j], b_f = bf[l * HDIM + j];
    const float b_o = bo[l * HDIM + j], b_c = bc[l * HDIM + j];

    float* cl = crun + (size_t)l * BATCH * HDIM;
    const float* colds = (t == 0) ? (c0 + (size_t)l * BATCH * HDIM) : cl;
    float* hdst = hseq + ((size_t)l * TIME + t) * BATCH * HDIM;
    const bool last = (l == LAYERS - 1);

    #pragma unroll
    for (int i = 0; i < 8; i++) {
        const int row = r0 + 8 * i;
        const int b   = b0 + row;
        const float su = gs[row * GS_STRIDE +      jj] + b_u;
        const float sf = gs[row * GS_STRIDE + 32 + jj] + b_f;
        const float so = gs[row * GS_STRIDE + 64 + jj] + b_o;
        const float sc = gs[row * GS_STRIDE + 96 + jj] + b_c;
        const float u  = 1.0f / (1.0f + expf(-su));
        const float f  = 1.0f / (1.0f + expf(-sf));
        const float o  = 1.0f / (1.0f + expf(-so));
        const float ct = tanhf(sc);
        const size_t idx = (size_t)b * HDIM + j;
        const float c_new = f * colds[idx] + u * ct;
        const float h_new = o * tanhf(c_new);
        cl[idx] = c_new;
        hdst[(size_t)b * HDIM + j_p] = f2tf32f(h_new);
        if (last) {
            const size_t oidx = ((size_t)b * TIME + t) * HDIM + j;
            outH[oidx] = h_new;
            outC[oidx] = c_new;
            if (t == TIME - 1) { outHt[idx] = h_new; outCt[idx] = c_new; }
        }
    }

    // Publish: all writes visible, then bump this (cell, bblk) counter.
    __threadfence();
    __syncthreads();
    if (tid == 0) atomicAdd(&g_cnt[cell * 4 + bblk], 1);
}

extern "C" void kernel_launch(void* const* d_in, const int* in_sizes, int n_in,
                              void* d_out, int out_size) {
    const float* x  = (const float*)d_in[0];   // (B, T, E)
    const float* h0 = (const float*)d_in[1];   // (L, B, H)
    const float* c0 = (const float*)d_in[2];   // (L, B, H)
    const float* Wu = (const float*)d_in[3];   // (L, 2048, H)
    const float* bu = (const float*)d_in[4];   // (L, H)
    const float* Wf = (const float*)d_in[5];
    const float* bf = (const float*)d_in[6];
    const float* Wo = (const float*)d_in[7];
    const float* bo = (const float*)d_in[8];
    const float* Wc = (const float*)d_in[9];
    const float* bc = (const float*)d_in[10];

    float* out = (float*)d_out;
    float* outHidden = out;                                   // (B, T, H)
    float* outMem    = out + (size_t)BATCH * TIME * HDIM;     // (B, T, H)
    float* outHt     = out + (size_t)2 * BATCH * TIME * HDIM; // (B, 1, H)
    float* outCt     = outHt + (size_t)BATCH * HDIM;          // (B, 1, H)

    float *hseq, *crun, *w2, *xr, *h0r;
    int* cnt;
    cudaGetSymbolAddress((void**)&hseq, g_hseq);
    cudaGetSymbolAddress((void**)&crun, g_crun);
    cudaGetSymbolAddress((void**)&w2,   g_w2);
    cudaGetSymbolAddress((void**)&xr,   g_xr);
    cudaGetSymbolAddress((void**)&h0r,  g_h0r);
    cudaGetSymbolAddress((void**)&cnt,  g_cnt);

    // Reset dependency counters (capture-legal memset node).
    cudaMemsetAsync(cnt, 0, NCELLS * 4 * sizeof(int), 0);

    // Prep: pack weights + round/permute activations.
    prep_w<<<16384, 256>>>(Wu, Wf, Wo, Wc, w2, (size_t)4 * LAYERS * 1024 * 256);
    prep_act<<<2048, 256>>>((const float4*)x,  (float4*)xr,
                            (size_t)BATCH * TIME * EDIM / 8,
                            (const float4*)h0, (float4*)h0r,
                            (size_t)LAYERS * BATCH * HDIM / 8);

    const int GSMEM = STAGES * STAGE_F * 4;   // 86016 B
    cudaFuncSetAttribute(lstm_fused, cudaFuncAttributeMaxDynamicSharedMemorySize, GSMEM);

    // Single DAG launch: 64 cells x 128 CTAs in wavefront order.
    lstm_fused<<<NCELLS * 128, 256, GSMEM>>>(
        xr, h0r, c0, w2, bu, bf, bo, bc,
        crun, hseq, outHidden, outMem, outHt, outCt);
}